// round 8
// baseline (speedup 1.0000x reference)
#include <cuda_runtime.h>
#include <math.h>

// Problem constants
#define Bn   32
#define Cn   16
#define HWn  65536
#define T1   64                // tiles per batch, pass1 (1024 px/tile, 2 quad-iters)
#define T3   128               // tiles per batch, pass3 (512 px/tile)
#define PPB1 1024
#define PPB3 512
#define THR  128               // threads per block
#define NCHUNK 512             // 128-px chunks per batch

// Scratch (__device__ globals; fully overwritten each run)
__device__ float g_part[2][Bn][32][T1];     // [tensor][batch][slot:0-15 tot,16-31 cls0][tile]
__device__ float g_cnt[Bn][T1];             // class-0 count partials (z==0)
__device__ float g_dm[2][Bn][Cn];           // normalized mean difference vectors
__device__ unsigned int g_mask[Bn][NCHUNK * 4]; // ballot-encoded class mask
__device__ float g_msep[Bn * T3];           // per-block MSE partials
__device__ unsigned int g_done1;            // pass1 last-block counter
__device__ unsigned int g_done3;            // pass3 last-block counter

__device__ __forceinline__ float wred(float v) {
    v += __shfl_down_sync(0xFFFFFFFFu, v, 16);
    v += __shfl_down_sync(0xFFFFFFFFu, v, 8);
    v += __shfl_down_sync(0xFFFFFFFFu, v, 4);
    v += __shfl_down_sync(0xFFFFFFFFu, v, 2);
    v += __shfl_down_sync(0xFFFFFFFFu, v, 1);
    return v;
}
__device__ __forceinline__ double wredd(double v) {
    v += __shfl_down_sync(0xFFFFFFFFu, v, 16);
    v += __shfl_down_sync(0xFFFFFFFFu, v, 8);
    v += __shfl_down_sync(0xFFFFFFFFu, v, 4);
    v += __shfl_down_sync(0xFFFFFFFFu, v, 2);
    v += __shfl_down_sync(0xFFFFFFFFu, v, 1);
    return v;
}
__device__ __forceinline__ float4 ldcs4(const float* p) {
    return __ldcs((const float4*)p);
}

// Per-block dtype sniff (pass1 only): int64 targets with values in {0,1} have
// all odd 32-bit words zero; int32 targets have random labels there.
__device__ __forceinline__ int sniff_is32(const int* __restrict__ tw, int tid) {
    int any = 0;
#pragma unroll
    for (int i = tid; i < 512; i += THR) any |= tw[2 * i + 1];
    return __syncthreads_or(any);
}

__device__ __forceinline__ void load_cls4(const int* __restrict__ twb, int p, int is32,
                                          int& c0, int& c1, int& c2, int& c3) {
    if (is32) {
        int4 v = __ldcs((const int4*)(twb + p));
        c0 = v.x; c1 = v.y; c2 = v.z; c3 = v.w;
    } else {
        int4 a = __ldcs((const int4*)(twb + 2 * p));
        int4 b = __ldcs((const int4*)(twb + 2 * p + 4));
        c0 = a.x; c1 = a.z; c2 = b.x; c3 = b.z;
    }
}

// ---------------------------------------------------------------------------
// Pass 1: partial sums of L2-normalized features + class bitmask emission.
// Last block computes the dM vectors (replaces the finalize kernel).
// grid (T1, Bn, 2); 2 quad-iterations/thread, float4 loads.
// ---------------------------------------------------------------------------
__global__ void __launch_bounds__(THR, 5)
pass1_kernel(const float* __restrict__ S, const float* __restrict__ T,
             const int* __restrict__ TW) {
    const int tile = blockIdx.x, b = blockIdx.y, z = blockIdx.z;
    const int tid  = threadIdx.x;
    const int lane = tid & 31, w = tid >> 5;
    const int is32 = sniff_is32(TW, tid);

    const float* Xb  = (z ? T : S) + ((size_t)b << 20);
    const int*   twb = TW + (is32 ? ((size_t)b << 16) : ((size_t)b << 17));

    float at[Cn], a0[Cn];
#pragma unroll
    for (int c = 0; c < Cn; c++) { at[c] = 0.f; a0[c] = 0.f; }
    float cnt = 0.f;

#pragma unroll
    for (int it = 0; it < 2; ++it) {
        const int p = tile * PPB1 + it * (THR * 4) + tid * 4;

        int c0, c1, c2, c3;
        load_cls4(twb, p, is32, c0, c1, c2, c3);
        const float m0 = (c0 == 0) ? 1.f : 0.f;
        const float m1 = (c1 == 0) ? 1.f : 0.f;
        const float m2 = (c2 == 0) ? 1.f : 0.f;
        const float m3 = (c3 == 0) ? 1.f : 0.f;
        cnt += (m0 + m1) + (m2 + m3);

        // Emit ballot-encoded mask (z==0 only): chunk of 128 px per warp-iter,
        // word j bit L = (pixel chunk*128 + L*4 + j is class 0).
        const unsigned int w0 = __ballot_sync(0xFFFFFFFFu, c0 == 0);
        const unsigned int w1 = __ballot_sync(0xFFFFFFFFu, c1 == 0);
        const unsigned int w2 = __ballot_sync(0xFFFFFFFFu, c2 == 0);
        const unsigned int w3 = __ballot_sync(0xFFFFFFFFu, c3 == 0);
        if (z == 0 && lane < 4) {
            const int chunk = tile * 8 + it * 4 + w;
            const unsigned int wj = (lane == 0) ? w0 : (lane == 1) ? w1 : (lane == 2) ? w2 : w3;
            g_mask[b][chunk * 4 + lane] = wj;
        }

        float4 v[Cn];
#pragma unroll
        for (int c = 0; c < Cn; c++) v[c] = ldcs4(Xb + ((size_t)c << 16) + p);

        float n0 = 0.f, n1 = 0.f, n2 = 0.f, n3 = 0.f;
#pragma unroll
        for (int c = 0; c < Cn; c++) {
            n0 = fmaf(v[c].x, v[c].x, n0); n1 = fmaf(v[c].y, v[c].y, n1);
            n2 = fmaf(v[c].z, v[c].z, n2); n3 = fmaf(v[c].w, v[c].w, n3);
        }
        const float i0 = rsqrtf(fmaxf(n0, 1e-24f));
        const float i1 = rsqrtf(fmaxf(n1, 1e-24f));
        const float i2 = rsqrtf(fmaxf(n2, 1e-24f));
        const float i3 = rsqrtf(fmaxf(n3, 1e-24f));

#pragma unroll
        for (int c = 0; c < Cn; c++) {
            const float f0 = v[c].x * i0, f1 = v[c].y * i1;
            const float f2 = v[c].z * i2, f3 = v[c].w * i3;
            at[c] += (f0 + f1) + (f2 + f3);
            a0[c] += (m0 * f0 + m1 * f1) + (m2 * f2 + m3 * f3);
        }
    }

    // Block reduce 33 slots; write partials.
    __shared__ float sred[THR / 32][33];
#pragma unroll
    for (int c = 0; c < Cn; c++) { at[c] = wred(at[c]); a0[c] = wred(a0[c]); }
    cnt = wred(cnt);
    if (lane == 0) {
#pragma unroll
        for (int c = 0; c < Cn; c++) { sred[w][c] = at[c]; sred[w][16 + c] = a0[c]; }
        sred[w][32] = cnt;
    }
    __syncthreads();
    if (tid < 33) {
        float s = 0.f;
#pragma unroll
        for (int ww = 0; ww < THR / 32; ww++) s += sred[ww][tid];
        if (tid < 32)      g_part[z][b][tid][tile] = s;
        else if (z == 0)   g_cnt[b][tile] = s;
    }

    // ---- Embedded finalize: last block computes dM while the grid drains ----
    __shared__ unsigned int slast;
    __syncthreads();
    if (tid == 0) {
        __threadfence();
        const unsigned int old = atomicAdd(&g_done1, 1u);
        slast = (old == (unsigned int)(T1 * Bn * 2 - 1)) ? 1u : 0u;
    }
    __syncthreads();
    if (!slast) return;

    __shared__ float scomb[2048];           // (z,b,slot) sums
    __shared__ float scnt2[Bn];
    __shared__ float smn[2][Bn][2][Cn];     // means
    __shared__ float srn[2][Bn][2];         // 1/||mean||
    for (int k = tid; k < 2048; k += THR) {
        const int zz = k >> 10, bb = (k >> 5) & 31, slot = k & 31;
        const float* bp = &g_part[zz][bb][slot][0];
        float a = 0.f;
#pragma unroll
        for (int t = 0; t < T1 / 4; t++) {
            const float4 vv = *(const float4*)(bp + 4 * t);
            a += (vv.x + vv.y) + (vv.z + vv.w);
        }
        scomb[k] = a;
    }
    for (int k = tid; k < Bn; k += THR) {
        const float* cp = &g_cnt[k][0];
        float a = 0.f;
#pragma unroll
        for (int t = 0; t < T1 / 4; t++) {
            const float4 vv = *(const float4*)(cp + 4 * t);
            a += (vv.x + vv.y) + (vv.z + vv.w);
        }
        scnt2[k] = a;
    }
    __syncthreads();
    {   // 128 threads = (z, b, cls)
        const int zz = tid >> 6, bb = (tid >> 1) & 31, cls = tid & 1;
        const float cnt0 = scnt2[bb];
        const float cv   = cls ? ((float)HWn - cnt0) : cnt0;
        const float inv  = 1.0f / (cv + 1e-6f);
        const float* base = &scomb[(zz * 32 + bb) * 32];
        float nm2 = 0.f;
#pragma unroll
        for (int c = 0; c < Cn; c++) {
            const float tot = base[c], s0 = base[16 + c];
            const float sv  = cls ? (tot - s0) : s0;
            const float m   = sv * inv;
            smn[zz][bb][cls][c] = m;
            nm2 = fmaf(m, m, nm2);
        }
        srn[zz][bb][cls] = 1.0f / fmaxf(sqrtf(nm2), 1e-8f);
    }
    __syncthreads();
    for (int k = tid; k < 2 * Bn * Cn; k += THR) {
        const int zz = k >> 9, bb = (k >> 4) & 31, c = k & 15;
        g_dm[zz][bb][c] = smn[zz][bb][0][c] * srn[zz][bb][0]
                        - smn[zz][bb][1][c] * srn[zz][bb][1];
    }
    if (tid == 0) g_done1 = 0;   // reset for next graph replay
}

// ---------------------------------------------------------------------------
// Pass 3: cd = dot(v, dM) * rsqrt(||v||^2); pcsim = exp(+-cd); MSE.
// grid (T3, Bn); 4 px/thread, float4 loads; target read from compact bitmask.
// ---------------------------------------------------------------------------
__global__ void __launch_bounds__(THR, 10)
pass3_kernel(const float* __restrict__ S, const float* __restrict__ T,
             float* __restrict__ out) {
    const int tile = blockIdx.x, b = blockIdx.y;
    const int tid  = threadIdx.x;
    const int lane = tid & 31, w = tid >> 5;

    __shared__ float sdM[2][Cn];
    __shared__ unsigned int slast;
    if (tid < 32) {
        const int z = tid >> 4, c = tid & 15;
        sdM[z][c] = g_dm[z][b][c];
    }
    __syncthreads();

    const float* Sb = S + ((size_t)b << 20);
    const float* Tb = T + ((size_t)b << 20);

    const int p = tile * PPB3 + tid * 4;
    const int chunk = tile * 4 + w;
    const uint4 mw = *(const uint4*)(&g_mask[b][chunk * 4]);
    const float s0 = ((mw.x >> lane) & 1u) ? 1.f : -1.f;
    const float s1 = ((mw.y >> lane) & 1u) ? 1.f : -1.f;
    const float s2 = ((mw.z >> lane) & 1u) ? 1.f : -1.f;
    const float s3 = ((mw.w >> lane) & 1u) ? 1.f : -1.f;

    float pcS0, pcS1, pcS2, pcS3;
    {   // ---- S ----
        float n0 = 0.f, n1 = 0.f, n2 = 0.f, n3 = 0.f;
        float d0 = 0.f, d1 = 0.f, d2 = 0.f, d3 = 0.f;
#pragma unroll
        for (int c = 0; c < Cn; c++) {
            const float4 v = ldcs4(Sb + ((size_t)c << 16) + p);
            const float m = sdM[0][c];
            n0 = fmaf(v.x, v.x, n0); n1 = fmaf(v.y, v.y, n1);
            n2 = fmaf(v.z, v.z, n2); n3 = fmaf(v.w, v.w, n3);
            d0 = fmaf(v.x, m, d0); d1 = fmaf(v.y, m, d1);
            d2 = fmaf(v.z, m, d2); d3 = fmaf(v.w, m, d3);
        }
        pcS0 = __expf(s0 * d0 * rsqrtf(fmaxf(n0, 1e-24f)));
        pcS1 = __expf(s1 * d1 * rsqrtf(fmaxf(n1, 1e-24f)));
        pcS2 = __expf(s2 * d2 * rsqrtf(fmaxf(n2, 1e-24f)));
        pcS3 = __expf(s3 * d3 * rsqrtf(fmaxf(n3, 1e-24f)));
    }
    float acc;
    {   // ---- T ----
        float n0 = 0.f, n1 = 0.f, n2 = 0.f, n3 = 0.f;
        float d0 = 0.f, d1 = 0.f, d2 = 0.f, d3 = 0.f;
#pragma unroll
        for (int c = 0; c < Cn; c++) {
            const float4 v = ldcs4(Tb + ((size_t)c << 16) + p);
            const float m = sdM[1][c];
            n0 = fmaf(v.x, v.x, n0); n1 = fmaf(v.y, v.y, n1);
            n2 = fmaf(v.z, v.z, n2); n3 = fmaf(v.w, v.w, n3);
            d0 = fmaf(v.x, m, d0); d1 = fmaf(v.y, m, d1);
            d2 = fmaf(v.z, m, d2); d3 = fmaf(v.w, m, d3);
        }
        const float e0 = pcS0 - __expf(s0 * d0 * rsqrtf(fmaxf(n0, 1e-24f)));
        const float e1 = pcS1 - __expf(s1 * d1 * rsqrtf(fmaxf(n1, 1e-24f)));
        const float e2 = pcS2 - __expf(s2 * d2 * rsqrtf(fmaxf(n2, 1e-24f)));
        const float e3 = pcS3 - __expf(s3 * d3 * rsqrtf(fmaxf(n3, 1e-24f)));
        acc = fmaf(e0, e0, e1 * e1) + fmaf(e2, e2, e3 * e3);
    }

    // Block reduce MSE partial, then last-block final reduction.
    __shared__ float smse[THR / 32];
    acc = wred(acc);
    if (lane == 0) smse[w] = acc;
    __syncthreads();
    const int gid = b * T3 + tile;
    if (tid == 0) {
        float sv = 0.f;
#pragma unroll
        for (int ww = 0; ww < THR / 32; ww++) sv += smse[ww];
        g_msep[gid] = sv;
        __threadfence();
        const unsigned int old = atomicAdd(&g_done3, 1u);
        slast = (old == (unsigned int)(Bn * T3 - 1)) ? 1u : 0u;
    }
    __syncthreads();

    if (slast) {
        volatile float* mp = &g_msep[0];
        double d = 0.0;
#pragma unroll
        for (int k = 0; k < (Bn * T3) / THR; k++)
            d += (double)mp[tid * ((Bn * T3) / THR) + k];
        d = wredd(d);
        __shared__ double sd[THR / 32];
        if (lane == 0) sd[w] = d;
        __syncthreads();
        if (tid == 0) {
            double tot = 0.0;
#pragma unroll
            for (int ww = 0; ww < THR / 32; ww++) tot += sd[ww];
            out[0] = (float)(tot * (1.0 / ((double)Bn * (double)HWn)));
            g_done3 = 0;   // reset for next graph replay
        }
    }
}

extern "C" void kernel_launch(void* const* d_in, const int* in_sizes, int n_in,
                              void* d_out, int out_size) {
    const float* S  = (const float*)d_in[0];
    const float* T  = (const float*)d_in[1];
    const int*   TW = (const int*)d_in[2];
    float* out = (float*)d_out;

    dim3 g1(T1, Bn, 2);
    pass1_kernel<<<g1, THR>>>(S, T, TW);
    dim3 g3(T3, Bn);
    pass3_kernel<<<g3, THR>>>(S, T, out);
}

// round 9
// speedup vs baseline: 1.2363x; 1.2363x over previous
#include <cuda_runtime.h>
#include <math.h>

// Problem constants
#define Bn   32
#define Cn   16
#define HWn  65536
#define T1   64                // tiles per batch, pass1 (1024 px/tile, 2 quad-iters)
#define T3   128               // tiles per batch, pass3 (512 px/tile)
#define PPB1 1024
#define PPB3 512
#define THR  128               // threads per block

// Scratch (__device__ globals; fully overwritten each run)
__device__ float g_part[2][Bn][32][T1];   // [tensor][batch][slot:0-15 tot,16-31 cls0][tile]
__device__ float g_cnt[Bn][T1];           // class-0 count partials (z==0)
__device__ float g_dm[2][Bn][Cn];         // normalized mean difference vectors
__device__ float g_msep[Bn * T3];         // per-block MSE partials
__device__ unsigned int g_done;           // last-block counter (self-resetting)

__device__ __forceinline__ float wred(float v) {
    v += __shfl_down_sync(0xFFFFFFFFu, v, 16);
    v += __shfl_down_sync(0xFFFFFFFFu, v, 8);
    v += __shfl_down_sync(0xFFFFFFFFu, v, 4);
    v += __shfl_down_sync(0xFFFFFFFFu, v, 2);
    v += __shfl_down_sync(0xFFFFFFFFu, v, 1);
    return v;
}
__device__ __forceinline__ double wredd(double v) {
    v += __shfl_down_sync(0xFFFFFFFFu, v, 16);
    v += __shfl_down_sync(0xFFFFFFFFu, v, 8);
    v += __shfl_down_sync(0xFFFFFFFFu, v, 4);
    v += __shfl_down_sync(0xFFFFFFFFu, v, 2);
    v += __shfl_down_sync(0xFFFFFFFFu, v, 1);
    return v;
}
__device__ __forceinline__ float4 ldcs4(const float* p) {
    return __ldcs((const float4*)p);
}

// Per-block dtype sniff: int64 targets with values in {0,1} have all odd
// 32-bit words zero; int32 targets have random labels there. All blocks read
// the same 512 words (L2-broadcast) -> identical deterministic result.
__device__ __forceinline__ int sniff_is32(const int* __restrict__ tw, int tid) {
    int any = 0;
#pragma unroll
    for (int i = tid; i < 512; i += THR) any |= tw[2 * i + 1];
    return __syncthreads_or(any);
}

__device__ __forceinline__ void load_cls4(const int* __restrict__ twb, int p, int is32,
                                          int& c0, int& c1, int& c2, int& c3) {
    if (is32) {
        int4 v = __ldcs((const int4*)(twb + p));
        c0 = v.x; c1 = v.y; c2 = v.z; c3 = v.w;
    } else {
        int4 a = __ldcs((const int4*)(twb + 2 * p));
        int4 b = __ldcs((const int4*)(twb + 2 * p + 4));
        c0 = a.x; c1 = a.z; c2 = b.x; c3 = b.z;
    }
}

// ---------------------------------------------------------------------------
// Pass 1: per-(tensor,batch,tile) partial sums of L2-normalized features.
// grid (T1, Bn, 2); 2 quad-iterations/thread, float4 loads. (R7, unchanged)
// ---------------------------------------------------------------------------
__global__ void __launch_bounds__(THR, 5)
pass1_kernel(const float* __restrict__ S, const float* __restrict__ T,
             const int* __restrict__ TW) {
    const int tile = blockIdx.x, b = blockIdx.y, z = blockIdx.z;
    const int tid  = threadIdx.x;
    const int is32 = sniff_is32(TW, tid);

    const float* Xb  = (z ? T : S) + ((size_t)b << 20);
    const int*   twb = TW + (is32 ? ((size_t)b << 16) : ((size_t)b << 17));

    float at[Cn], a0[Cn];
#pragma unroll
    for (int c = 0; c < Cn; c++) { at[c] = 0.f; a0[c] = 0.f; }
    float cnt = 0.f;

#pragma unroll
    for (int it = 0; it < 2; ++it) {
        const int p = tile * PPB1 + it * (THR * 4) + tid * 4;

        int c0, c1, c2, c3;
        load_cls4(twb, p, is32, c0, c1, c2, c3);
        const float m0 = (c0 == 0) ? 1.f : 0.f;
        const float m1 = (c1 == 0) ? 1.f : 0.f;
        const float m2 = (c2 == 0) ? 1.f : 0.f;
        const float m3 = (c3 == 0) ? 1.f : 0.f;
        cnt += (m0 + m1) + (m2 + m3);

        float4 v[Cn];
#pragma unroll
        for (int c = 0; c < Cn; c++) v[c] = ldcs4(Xb + ((size_t)c << 16) + p);

        float n0 = 0.f, n1 = 0.f, n2 = 0.f, n3 = 0.f;
#pragma unroll
        for (int c = 0; c < Cn; c++) {
            n0 = fmaf(v[c].x, v[c].x, n0); n1 = fmaf(v[c].y, v[c].y, n1);
            n2 = fmaf(v[c].z, v[c].z, n2); n3 = fmaf(v[c].w, v[c].w, n3);
        }
        const float i0 = rsqrtf(fmaxf(n0, 1e-24f));
        const float i1 = rsqrtf(fmaxf(n1, 1e-24f));
        const float i2 = rsqrtf(fmaxf(n2, 1e-24f));
        const float i3 = rsqrtf(fmaxf(n3, 1e-24f));

#pragma unroll
        for (int c = 0; c < Cn; c++) {
            const float f0 = v[c].x * i0, f1 = v[c].y * i1;
            const float f2 = v[c].z * i2, f3 = v[c].w * i3;
            at[c] += (f0 + f1) + (f2 + f3);
            a0[c] += (m0 * f0 + m1 * f1) + (m2 * f2 + m3 * f3);
        }
    }

    // Block reduce 33 slots; write partials (no atomics).
    __shared__ float sred[THR / 32][33];
    const int lane = tid & 31, w = tid >> 5;
#pragma unroll
    for (int c = 0; c < Cn; c++) { at[c] = wred(at[c]); a0[c] = wred(a0[c]); }
    cnt = wred(cnt);
    if (lane == 0) {
#pragma unroll
        for (int c = 0; c < Cn; c++) { sred[w][c] = at[c]; sred[w][16 + c] = a0[c]; }
        sred[w][32] = cnt;
    }
    __syncthreads();
    if (tid < 33) {
        float s = 0.f;
#pragma unroll
        for (int ww = 0; ww < THR / 32; ww++) s += sred[ww][tid];
        if (tid < 32)      g_part[z][b][tid][tile] = s;
        else if (z == 0)   g_cnt[b][tile] = s;
    }
}

// ---------------------------------------------------------------------------
// Finalize: reduce tile partials -> normalized mean-difference vectors dM.
// grid (Bn, 2), 256 threads. (R7, unchanged)
// ---------------------------------------------------------------------------
__global__ void finalize_kernel() {
    const int b = blockIdx.x, z = blockIdx.y;
    const int tid = threadIdx.x;

    __shared__ float s[8][32];
    __shared__ float sc[8];
    __shared__ float red[32];
    __shared__ float scnt;
    __shared__ float smean[2][Cn];
    __shared__ float srn[2];

    {   // 256 threads = 32 slots x 8 groups of 8 tiles
        const int slot = tid & 31, g = tid >> 5;
        const float* base = &g_part[z][b][slot][0] + g * 8;
        float a = 0.f;
#pragma unroll
        for (int k = 0; k < 2; k++) {
            const float4 v = *(const float4*)(base + 4 * k);
            a += (v.x + v.y) + (v.z + v.w);
        }
        s[g][slot] = a;
    }
    if (tid < 8) {
        const float* cb = &g_cnt[b][0] + tid * 8;
        float a = 0.f;
#pragma unroll
        for (int k = 0; k < 2; k++) {
            const float4 v = *(const float4*)(cb + 4 * k);
            a += (v.x + v.y) + (v.z + v.w);
        }
        sc[tid] = a;
    }
    __syncthreads();
    if (tid < 32) {
        float a = 0.f;
#pragma unroll
        for (int g = 0; g < 8; g++) a += s[g][tid];
        red[tid] = a;
    } else if (tid == 32) {
        float a = 0.f;
#pragma unroll
        for (int g = 0; g < 8; g++) a += sc[g];
        scnt = a;
    }
    __syncthreads();
    if (tid < 2) {
        const int cls = tid;
        const float cnt0 = scnt;
        const float cnt  = cls ? ((float)HWn - cnt0) : cnt0;
        const float inv  = 1.0f / (cnt + 1e-6f);
        float nm2 = 0.f;
#pragma unroll
        for (int c = 0; c < Cn; c++) {
            const float tot = red[c], s0 = red[16 + c];
            const float sv  = cls ? (tot - s0) : s0;
            const float m   = sv * inv;
            smean[cls][c] = m;
            nm2 = fmaf(m, m, nm2);
        }
        srn[cls] = 1.0f / fmaxf(sqrtf(nm2), 1e-8f);
    }
    __syncthreads();
    if (tid < Cn) {
        g_dm[z][b][tid] = smean[0][tid] * srn[0] - smean[1][tid] * srn[1];
    }
}

// ---------------------------------------------------------------------------
// Pass 3: S and T loads INTERLEAVED in one channel loop -> 32 outstanding
// LDG.128 per thread before any dependent math. grid (T3, Bn); 4 px/thread.
// ---------------------------------------------------------------------------
__global__ void __launch_bounds__(THR, 8)
pass3_kernel(const float* __restrict__ S, const float* __restrict__ T,
             const int* __restrict__ TW, float* __restrict__ out) {
    const int tile = blockIdx.x, b = blockIdx.y;
    const int tid  = threadIdx.x;
    const int is32 = sniff_is32(TW, tid);

    __shared__ float sdM[2][Cn];
    __shared__ unsigned int slast;
    if (tid < 32) {
        const int z = tid >> 4, c = tid & 15;
        sdM[z][c] = g_dm[z][b][c];
    }
    __syncthreads();

    const float* Sb  = S + ((size_t)b << 20);
    const float* Tb  = T + ((size_t)b << 20);
    const int*   twb = TW + (is32 ? ((size_t)b << 16) : ((size_t)b << 17));

    const int p = tile * PPB3 + tid * 4;
    int c0, c1, c2, c3;
    load_cls4(twb, p, is32, c0, c1, c2, c3);
    const float s0 = (c0 == 0) ? 1.f : -1.f;
    const float s1 = (c1 == 0) ? 1.f : -1.f;
    const float s2 = (c2 == 0) ? 1.f : -1.f;
    const float s3 = (c3 == 0) ? 1.f : -1.f;

    // Interleaved S/T channel loop: independent accumulator sets.
    float nS0 = 0.f, nS1 = 0.f, nS2 = 0.f, nS3 = 0.f;
    float dS0 = 0.f, dS1 = 0.f, dS2 = 0.f, dS3 = 0.f;
    float nT0 = 0.f, nT1 = 0.f, nT2 = 0.f, nT3 = 0.f;
    float dT0 = 0.f, dT1 = 0.f, dT2 = 0.f, dT3 = 0.f;
#pragma unroll
    for (int c = 0; c < Cn; c++) {
        const float4 vs = ldcs4(Sb + ((size_t)c << 16) + p);
        const float4 vt = ldcs4(Tb + ((size_t)c << 16) + p);
        const float mS = sdM[0][c], mT = sdM[1][c];
        nS0 = fmaf(vs.x, vs.x, nS0); nS1 = fmaf(vs.y, vs.y, nS1);
        nS2 = fmaf(vs.z, vs.z, nS2); nS3 = fmaf(vs.w, vs.w, nS3);
        dS0 = fmaf(vs.x, mS, dS0);   dS1 = fmaf(vs.y, mS, dS1);
        dS2 = fmaf(vs.z, mS, dS2);   dS3 = fmaf(vs.w, mS, dS3);
        nT0 = fmaf(vt.x, vt.x, nT0); nT1 = fmaf(vt.y, vt.y, nT1);
        nT2 = fmaf(vt.z, vt.z, nT2); nT3 = fmaf(vt.w, vt.w, nT3);
        dT0 = fmaf(vt.x, mT, dT0);   dT1 = fmaf(vt.y, mT, dT1);
        dT2 = fmaf(vt.z, mT, dT2);   dT3 = fmaf(vt.w, mT, dT3);
    }

    const float e0 = __expf(s0 * dS0 * rsqrtf(fmaxf(nS0, 1e-24f)))
                   - __expf(s0 * dT0 * rsqrtf(fmaxf(nT0, 1e-24f)));
    const float e1 = __expf(s1 * dS1 * rsqrtf(fmaxf(nS1, 1e-24f)))
                   - __expf(s1 * dT1 * rsqrtf(fmaxf(nT1, 1e-24f)));
    const float e2 = __expf(s2 * dS2 * rsqrtf(fmaxf(nS2, 1e-24f)))
                   - __expf(s2 * dT2 * rsqrtf(fmaxf(nT2, 1e-24f)));
    const float e3 = __expf(s3 * dS3 * rsqrtf(fmaxf(nS3, 1e-24f)))
                   - __expf(s3 * dT3 * rsqrtf(fmaxf(nT3, 1e-24f)));
    float acc = fmaf(e0, e0, e1 * e1) + fmaf(e2, e2, e3 * e3);

    // Block reduce MSE partial, then last-block final reduction.
    __shared__ float smse[THR / 32];
    acc = wred(acc);
    const int lane = tid & 31, w = tid >> 5;
    if (lane == 0) smse[w] = acc;
    __syncthreads();
    const int gid = b * T3 + tile;
    if (tid == 0) {
        float sv = 0.f;
#pragma unroll
        for (int ww = 0; ww < THR / 32; ww++) sv += smse[ww];
        g_msep[gid] = sv;
        __threadfence();
        const unsigned int old = atomicAdd(&g_done, 1u);
        slast = (old == (unsigned int)(Bn * T3 - 1)) ? 1u : 0u;
    }
    __syncthreads();

    if (slast) {
        volatile float* mp = &g_msep[0];
        double d = 0.0;
#pragma unroll
        for (int k = 0; k < (Bn * T3) / THR; k++)
            d += (double)mp[tid * ((Bn * T3) / THR) + k];
        d = wredd(d);
        __shared__ double sd[THR / 32];
        if (lane == 0) sd[w] = d;
        __syncthreads();
        if (tid == 0) {
            double tot = 0.0;
#pragma unroll
            for (int ww = 0; ww < THR / 32; ww++) tot += sd[ww];
            out[0] = (float)(tot * (1.0 / ((double)Bn * (double)HWn)));
            g_done = 0;   // reset for next graph replay
        }
    }
}

extern "C" void kernel_launch(void* const* d_in, const int* in_sizes, int n_in,
                              void* d_out, int out_size) {
    const float* S  = (const float*)d_in[0];
    const float* T  = (const float*)d_in[1];
    const int*   TW = (const int*)d_in[2];
    float* out = (float*)d_out;

    dim3 g1(T1, Bn, 2);
    pass1_kernel<<<g1, THR>>>(S, T, TW);
    dim3 gf(Bn, 2);
    finalize_kernel<<<gf, 256>>>();
    dim3 g3(T3, Bn);
    pass3_kernel<<<g3, THR>>>(S, T, TW, out);
}

// round 10
// speedup vs baseline: 1.2530x; 1.0135x over previous
#include <cuda_runtime.h>
#include <math.h>

// Problem constants
#define Bn   32
#define Cn   16
#define HWn  65536
#define T1   128               // tiles per batch, pass1 (512 px/tile)
#define T3   128               // tiles per batch, pass3 (512 px/tile)
#define PPB  512               // pixels per block
#define THR  128               // threads per block; 4 px/thread, float4

// Scratch (__device__ globals; fully overwritten each run)
__device__ float g_part[2][Bn][32][T1];   // [tensor][batch][slot:0-15 tot,16-31 cls0][tile]
__device__ float g_cnt[Bn][T1];           // class-0 count partials (z==0)
__device__ float g_dm[2][Bn][Cn];         // normalized mean difference vectors
__device__ float g_msep[Bn * T3];         // per-block MSE partials
__device__ int   g_is32;                  // target dtype flag (written by pass1)
__device__ unsigned int g_done;           // last-block counter (self-resetting)

__device__ __forceinline__ float wred(float v) {
    v += __shfl_down_sync(0xFFFFFFFFu, v, 16);
    v += __shfl_down_sync(0xFFFFFFFFu, v, 8);
    v += __shfl_down_sync(0xFFFFFFFFu, v, 4);
    v += __shfl_down_sync(0xFFFFFFFFu, v, 2);
    v += __shfl_down_sync(0xFFFFFFFFu, v, 1);
    return v;
}
__device__ __forceinline__ double wredd(double v) {
    v += __shfl_down_sync(0xFFFFFFFFu, v, 16);
    v += __shfl_down_sync(0xFFFFFFFFu, v, 8);
    v += __shfl_down_sync(0xFFFFFFFFu, v, 4);
    v += __shfl_down_sync(0xFFFFFFFFu, v, 2);
    v += __shfl_down_sync(0xFFFFFFFFu, v, 1);
    return v;
}
__device__ __forceinline__ float4 ldcs4(const float* p) {
    return __ldcs((const float4*)p);
}

// Per-block dtype sniff (pass1 only): int64 targets with values in {0,1} have
// all odd 32-bit words zero; int32 targets have random labels there. All
// blocks read the same 512 words (L2-broadcast) -> identical result.
__device__ __forceinline__ int sniff_is32(const int* __restrict__ tw, int tid) {
    int any = 0;
#pragma unroll
    for (int i = tid; i < 512; i += THR) any |= tw[2 * i + 1];
    return __syncthreads_or(any);
}

__device__ __forceinline__ void load_cls4(const int* __restrict__ twb, int p, int is32,
                                          int& c0, int& c1, int& c2, int& c3) {
    if (is32) {
        int4 v = __ldg((const int4*)(twb + p));
        c0 = v.x; c1 = v.y; c2 = v.z; c3 = v.w;
    } else {
        int4 a = __ldg((const int4*)(twb + 2 * p));
        int4 b = __ldg((const int4*)(twb + 2 * p + 4));
        c0 = a.x; c1 = a.z; c2 = b.x; c3 = b.z;
    }
}

// ---------------------------------------------------------------------------
// Pass 1 (R6 proven-best shape): per-(tensor,batch,tile) partial sums of
// L2-normalized features. grid (T1, Bn, 2); 4 px/thread, float4, 1 iteration.
// ---------------------------------------------------------------------------
__global__ void __launch_bounds__(THR, 4)
pass1_kernel(const float* __restrict__ S, const float* __restrict__ T,
             const int* __restrict__ TW) {
    const int tile = blockIdx.x, b = blockIdx.y, z = blockIdx.z;
    const int tid  = threadIdx.x;
    const int is32 = sniff_is32(TW, tid);
    if (tid == 0) g_is32 = is32;   // same value from every block (benign race)

    const float* Xb  = (z ? T : S) + ((size_t)b << 20);
    const int*   twb = TW + (is32 ? ((size_t)b << 16) : ((size_t)b << 17));

    const int p = tile * PPB + tid * 4;
    int c0, c1, c2, c3;
    load_cls4(twb, p, is32, c0, c1, c2, c3);
    const float m0 = (c0 == 0) ? 1.f : 0.f;
    const float m1 = (c1 == 0) ? 1.f : 0.f;
    const float m2 = (c2 == 0) ? 1.f : 0.f;
    const float m3 = (c3 == 0) ? 1.f : 0.f;
    float cnt = (m0 + m1) + (m2 + m3);

    float4 v[Cn];
#pragma unroll
    for (int c = 0; c < Cn; c++) v[c] = ldcs4(Xb + ((size_t)c << 16) + p);

    float n0 = 0.f, n1 = 0.f, n2 = 0.f, n3 = 0.f;
#pragma unroll
    for (int c = 0; c < Cn; c++) {
        n0 = fmaf(v[c].x, v[c].x, n0); n1 = fmaf(v[c].y, v[c].y, n1);
        n2 = fmaf(v[c].z, v[c].z, n2); n3 = fmaf(v[c].w, v[c].w, n3);
    }
    const float i0 = rsqrtf(fmaxf(n0, 1e-24f));
    const float i1 = rsqrtf(fmaxf(n1, 1e-24f));
    const float i2 = rsqrtf(fmaxf(n2, 1e-24f));
    const float i3 = rsqrtf(fmaxf(n3, 1e-24f));

    float at[Cn], a0[Cn];
#pragma unroll
    for (int c = 0; c < Cn; c++) {
        const float f0 = v[c].x * i0, f1 = v[c].y * i1;
        const float f2 = v[c].z * i2, f3 = v[c].w * i3;
        at[c] = (f0 + f1) + (f2 + f3);
        a0[c] = (m0 * f0 + m1 * f1) + (m2 * f2 + m3 * f3);
    }

    // Block reduce 33 slots; write partials (no atomics).
    __shared__ float sred[THR / 32][33];
    const int lane = tid & 31, w = tid >> 5;
#pragma unroll
    for (int c = 0; c < Cn; c++) { at[c] = wred(at[c]); a0[c] = wred(a0[c]); }
    cnt = wred(cnt);
    if (lane == 0) {
#pragma unroll
        for (int c = 0; c < Cn; c++) { sred[w][c] = at[c]; sred[w][16 + c] = a0[c]; }
        sred[w][32] = cnt;
    }
    __syncthreads();
    if (tid < 33) {
        float s = 0.f;
#pragma unroll
        for (int ww = 0; ww < THR / 32; ww++) s += sred[ww][tid];
        if (tid < 32)      g_part[z][b][tid][tile] = s;
        else if (z == 0)   g_cnt[b][tile] = s;
    }
}

// ---------------------------------------------------------------------------
// Finalize: reduce tile partials -> normalized mean-difference vectors dM.
// grid (Bn, 2), 256 threads.
// ---------------------------------------------------------------------------
__global__ void finalize_kernel() {
    const int b = blockIdx.x, z = blockIdx.y;
    const int tid = threadIdx.x;

    __shared__ float s[8][32];
    __shared__ float sc[8];
    __shared__ float red[32];
    __shared__ float scnt;
    __shared__ float smean[2][Cn];
    __shared__ float srn[2];

    {   // 256 threads = 32 slots x 8 groups of 16 tiles
        const int slot = tid & 31, g = tid >> 5;
        const float* base = &g_part[z][b][slot][0] + g * 16;
        float a = 0.f;
#pragma unroll
        for (int k = 0; k < 4; k++) {
            const float4 v = *(const float4*)(base + 4 * k);
            a += (v.x + v.y) + (v.z + v.w);
        }
        s[g][slot] = a;
    }
    if (tid < 8) {
        const float* cb = &g_cnt[b][0] + tid * 16;
        float a = 0.f;
#pragma unroll
        for (int k = 0; k < 4; k++) {
            const float4 v = *(const float4*)(cb + 4 * k);
            a += (v.x + v.y) + (v.z + v.w);
        }
        sc[tid] = a;
    }
    __syncthreads();
    if (tid < 32) {
        float a = 0.f;
#pragma unroll
        for (int g = 0; g < 8; g++) a += s[g][tid];
        red[tid] = a;
    } else if (tid == 32) {
        float a = 0.f;
#pragma unroll
        for (int g = 0; g < 8; g++) a += sc[g];
        scnt = a;
    }
    __syncthreads();
    if (tid < 2) {
        const int cls = tid;
        const float cnt0 = scnt;
        const float cnt  = cls ? ((float)HWn - cnt0) : cnt0;
        const float inv  = 1.0f / (cnt + 1e-6f);
        float nm2 = 0.f;
#pragma unroll
        for (int c = 0; c < Cn; c++) {
            const float tot = red[c], s0 = red[16 + c];
            const float sv  = cls ? (tot - s0) : s0;
            const float m   = sv * inv;
            smean[cls][c] = m;
            nm2 = fmaf(m, m, nm2);
        }
        srn[cls] = 1.0f / fmaxf(sqrtf(nm2), 1e-8f);
    }
    __syncthreads();
    if (tid < Cn) {
        g_dm[z][b][tid] = smean[0][tid] * srn[0] - smean[1][tid] * srn[1];
    }
}

// ---------------------------------------------------------------------------
// Pass 3: interleaved S/T channel loop (32 outstanding LDG.128/thread);
// cd = dot(v, dM) * rsqrt(||v||^2); pcsim = exp(+-cd); MSE. No sniff loop.
// grid (T3, Bn); 4 px/thread, float4 loads.
// ---------------------------------------------------------------------------
__global__ void __launch_bounds__(THR, 8)
pass3_kernel(const float* __restrict__ S, const float* __restrict__ T,
             const int* __restrict__ TW, float* __restrict__ out) {
    const int tile = blockIdx.x, b = blockIdx.y;
    const int tid  = threadIdx.x;

    __shared__ float sdM[2][Cn];
    __shared__ int sis32;
    __shared__ unsigned int slast;
    if (tid < 32) {
        const int z = tid >> 4, c = tid & 15;
        sdM[z][c] = g_dm[z][b][c];
    } else if (tid == 32) {
        sis32 = g_is32;
    }
    __syncthreads();
    const int is32 = sis32;

    const float* Sb  = S + ((size_t)b << 20);
    const float* Tb  = T + ((size_t)b << 20);
    const int*   twb = TW + (is32 ? ((size_t)b << 16) : ((size_t)b << 17));

    const int p = tile * PPB + tid * 4;
    int c0, c1, c2, c3;
    load_cls4(twb, p, is32, c0, c1, c2, c3);
    const float s0 = (c0 == 0) ? 1.f : -1.f;
    const float s1 = (c1 == 0) ? 1.f : -1.f;
    const float s2 = (c2 == 0) ? 1.f : -1.f;
    const float s3 = (c3 == 0) ? 1.f : -1.f;

    // Interleaved S/T channel loop: independent accumulator sets.
    float nS0 = 0.f, nS1 = 0.f, nS2 = 0.f, nS3 = 0.f;
    float dS0 = 0.f, dS1 = 0.f, dS2 = 0.f, dS3 = 0.f;
    float nT0 = 0.f, nT1 = 0.f, nT2 = 0.f, nT3 = 0.f;
    float dT0 = 0.f, dT1 = 0.f, dT2 = 0.f, dT3 = 0.f;
#pragma unroll
    for (int c = 0; c < Cn; c++) {
        const float4 vs = ldcs4(Sb + ((size_t)c << 16) + p);
        const float4 vt = ldcs4(Tb + ((size_t)c << 16) + p);
        const float mS = sdM[0][c], mT = sdM[1][c];
        nS0 = fmaf(vs.x, vs.x, nS0); nS1 = fmaf(vs.y, vs.y, nS1);
        nS2 = fmaf(vs.z, vs.z, nS2); nS3 = fmaf(vs.w, vs.w, nS3);
        dS0 = fmaf(vs.x, mS, dS0);   dS1 = fmaf(vs.y, mS, dS1);
        dS2 = fmaf(vs.z, mS, dS2);   dS3 = fmaf(vs.w, mS, dS3);
        nT0 = fmaf(vt.x, vt.x, nT0); nT1 = fmaf(vt.y, vt.y, nT1);
        nT2 = fmaf(vt.z, vt.z, nT2); nT3 = fmaf(vt.w, vt.w, nT3);
        dT0 = fmaf(vt.x, mT, dT0);   dT1 = fmaf(vt.y, mT, dT1);
        dT2 = fmaf(vt.z, mT, dT2);   dT3 = fmaf(vt.w, mT, dT3);
    }

    const float e0 = __expf(s0 * dS0 * rsqrtf(fmaxf(nS0, 1e-24f)))
                   - __expf(s0 * dT0 * rsqrtf(fmaxf(nT0, 1e-24f)));
    const float e1 = __expf(s1 * dS1 * rsqrtf(fmaxf(nS1, 1e-24f)))
                   - __expf(s1 * dT1 * rsqrtf(fmaxf(nT1, 1e-24f)));
    const float e2 = __expf(s2 * dS2 * rsqrtf(fmaxf(nS2, 1e-24f)))
                   - __expf(s2 * dT2 * rsqrtf(fmaxf(nT2, 1e-24f)));
    const float e3 = __expf(s3 * dS3 * rsqrtf(fmaxf(nS3, 1e-24f)))
                   - __expf(s3 * dT3 * rsqrtf(fmaxf(nT3, 1e-24f)));
    float acc = fmaf(e0, e0, e1 * e1) + fmaf(e2, e2, e3 * e3);

    // Block reduce MSE partial, then last-block final reduction.
    __shared__ float smse[THR / 32];
    acc = wred(acc);
    const int lane = tid & 31, w = tid >> 5;
    if (lane == 0) smse[w] = acc;
    __syncthreads();
    const int gid = b * T3 + tile;
    if (tid == 0) {
        float sv = 0.f;
#pragma unroll
        for (int ww = 0; ww < THR / 32; ww++) sv += smse[ww];
        g_msep[gid] = sv;
        __threadfence();
        const unsigned int old = atomicAdd(&g_done, 1u);
        slast = (old == (unsigned int)(Bn * T3 - 1)) ? 1u : 0u;
    }
    __syncthreads();

    if (slast) {
        volatile float* mp = &g_msep[0];
        double d = 0.0;
#pragma unroll
        for (int k = 0; k < (Bn * T3) / THR; k++)
            d += (double)mp[tid * ((Bn * T3) / THR) + k];
        d = wredd(d);
        __shared__ double sd[THR / 32];
        if (lane == 0) sd[w] = d;
        __syncthreads();
        if (tid == 0) {
            double tot = 0.0;
#pragma unroll
            for (int ww = 0; ww < THR / 32; ww++) tot += sd[ww];
            out[0] = (float)(tot * (1.0 / ((double)Bn * (double)HWn)));
            g_done = 0;   // reset for next graph replay
        }
    }
}

extern "C" void kernel_launch(void* const* d_in, const int* in_sizes, int n_in,
                              void* d_out, int out_size) {
    const float* S  = (const float*)d_in[0];
    const float* T  = (const float*)d_in[1];
    const int*   TW = (const int*)d_in[2];
    float* out = (float*)d_out;

    dim3 g1(T1, Bn, 2);
    pass1_kernel<<<g1, THR>>>(S, T, TW);
    dim3 gf(Bn, 2);
    finalize_kernel<<<gf, 256>>>();
    dim3 g3(T3, Bn);
    pass3_kernel<<<g3, THR>>>(S, T, TW, out);
}

// round 11
// speedup vs baseline: 1.2617x; 1.0070x over previous
#include <cuda_runtime.h>
#include <math.h>

// Problem constants
#define Bn   32
#define Cn   16
#define HWn  65536
#define T1   128               // tiles per batch, pass1 (512 px/tile)
#define T3   128               // tiles per batch, pass3 (512 px/tile)
#define PPB  512               // pixels per block
#define THR  128               // threads per block; 4 px/thread, float4

// Scratch (__device__ globals; fully overwritten each run)
__device__ float g_part[2][Bn][32][T1];   // [tensor][batch][slot:0-15 tot,16-31 cls0][tile]
__device__ float g_cnt[Bn][T1];           // class-0 count partials (z==0)
__device__ float g_dm[2][Bn][Cn];         // normalized mean difference vectors
__device__ float g_msep[Bn * T3];         // per-block MSE partials
__device__ int   g_is32;                  // target dtype flag (written by pass1)
__device__ unsigned int g_done;           // last-block counter (self-resetting)

__device__ __forceinline__ float wred(float v) {
    v += __shfl_down_sync(0xFFFFFFFFu, v, 16);
    v += __shfl_down_sync(0xFFFFFFFFu, v, 8);
    v += __shfl_down_sync(0xFFFFFFFFu, v, 4);
    v += __shfl_down_sync(0xFFFFFFFFu, v, 2);
    v += __shfl_down_sync(0xFFFFFFFFu, v, 1);
    return v;
}
__device__ __forceinline__ double wredd(double v) {
    v += __shfl_down_sync(0xFFFFFFFFu, v, 16);
    v += __shfl_down_sync(0xFFFFFFFFu, v, 8);
    v += __shfl_down_sync(0xFFFFFFFFu, v, 4);
    v += __shfl_down_sync(0xFFFFFFFFu, v, 2);
    v += __shfl_down_sync(0xFFFFFFFFu, v, 1);
    return v;
}
__device__ __forceinline__ float4 ldcs4(const float* p) {
    return __ldcs((const float4*)p);
}

// Per-block dtype sniff (pass1 only): int64 targets with values in {0,1} have
// all odd 32-bit words zero; int32 targets have random labels there. All
// blocks read the same 512 words (L2-broadcast) -> identical result.
__device__ __forceinline__ int sniff_is32(const int* __restrict__ tw, int tid) {
    int any = 0;
#pragma unroll
    for (int i = tid; i < 512; i += THR) any |= tw[2 * i + 1];
    return __syncthreads_or(any);
}

__device__ __forceinline__ void load_cls4(const int* __restrict__ twb, int p, int is32,
                                          int& c0, int& c1, int& c2, int& c3) {
    if (is32) {
        int4 v = __ldg((const int4*)(twb + p));
        c0 = v.x; c1 = v.y; c2 = v.z; c3 = v.w;
    } else {
        int4 a = __ldg((const int4*)(twb + 2 * p));
        int4 b = __ldg((const int4*)(twb + 2 * p + 4));
        c0 = a.x; c1 = a.z; c2 = b.x; c3 = b.z;
    }
}

// ---------------------------------------------------------------------------
// Pass 1 (proven-best shape, unchanged from R10): partial sums of
// L2-normalized features. grid (T1, Bn, 2); 4 px/thread, float4, 1 iteration.
// ---------------------------------------------------------------------------
__global__ void __launch_bounds__(THR, 4)
pass1_kernel(const float* __restrict__ S, const float* __restrict__ T,
             const int* __restrict__ TW) {
    const int tile = blockIdx.x, b = blockIdx.y, z = blockIdx.z;
    const int tid  = threadIdx.x;
    const int is32 = sniff_is32(TW, tid);
    if (tid == 0) g_is32 = is32;   // same value from every block (benign race)

    const float* Xb  = (z ? T : S) + ((size_t)b << 20);
    const int*   twb = TW + (is32 ? ((size_t)b << 16) : ((size_t)b << 17));

    const int p = tile * PPB + tid * 4;
    int c0, c1, c2, c3;
    load_cls4(twb, p, is32, c0, c1, c2, c3);
    const float m0 = (c0 == 0) ? 1.f : 0.f;
    const float m1 = (c1 == 0) ? 1.f : 0.f;
    const float m2 = (c2 == 0) ? 1.f : 0.f;
    const float m3 = (c3 == 0) ? 1.f : 0.f;
    float cnt = (m0 + m1) + (m2 + m3);

    float4 v[Cn];
#pragma unroll
    for (int c = 0; c < Cn; c++) v[c] = ldcs4(Xb + ((size_t)c << 16) + p);

    float n0 = 0.f, n1 = 0.f, n2 = 0.f, n3 = 0.f;
#pragma unroll
    for (int c = 0; c < Cn; c++) {
        n0 = fmaf(v[c].x, v[c].x, n0); n1 = fmaf(v[c].y, v[c].y, n1);
        n2 = fmaf(v[c].z, v[c].z, n2); n3 = fmaf(v[c].w, v[c].w, n3);
    }
    const float i0 = rsqrtf(fmaxf(n0, 1e-24f));
    const float i1 = rsqrtf(fmaxf(n1, 1e-24f));
    const float i2 = rsqrtf(fmaxf(n2, 1e-24f));
    const float i3 = rsqrtf(fmaxf(n3, 1e-24f));

    float at[Cn], a0[Cn];
#pragma unroll
    for (int c = 0; c < Cn; c++) {
        const float f0 = v[c].x * i0, f1 = v[c].y * i1;
        const float f2 = v[c].z * i2, f3 = v[c].w * i3;
        at[c] = (f0 + f1) + (f2 + f3);
        a0[c] = (m0 * f0 + m1 * f1) + (m2 * f2 + m3 * f3);
    }

    // Block reduce 33 slots; write partials (no atomics).
    __shared__ float sred[THR / 32][33];
    const int lane = tid & 31, w = tid >> 5;
#pragma unroll
    for (int c = 0; c < Cn; c++) { at[c] = wred(at[c]); a0[c] = wred(a0[c]); }
    cnt = wred(cnt);
    if (lane == 0) {
#pragma unroll
        for (int c = 0; c < Cn; c++) { sred[w][c] = at[c]; sred[w][16 + c] = a0[c]; }
        sred[w][32] = cnt;
    }
    __syncthreads();
    if (tid < 33) {
        float s = 0.f;
#pragma unroll
        for (int ww = 0; ww < THR / 32; ww++) s += sred[ww][tid];
        if (tid < 32)      g_part[z][b][tid][tile] = s;
        else if (z == 0)   g_cnt[b][tile] = s;
    }
}

// ---------------------------------------------------------------------------
// Finalize (PDL secondary): waits on pass1, reduces tile partials -> dM.
// grid (Bn, 2), 256 threads.
// ---------------------------------------------------------------------------
__global__ void finalize_kernel() {
    // PDL: block until the upstream (pass1) grid's writes are visible.
    cudaGridDependencySynchronize();

    const int b = blockIdx.x, z = blockIdx.y;
    const int tid = threadIdx.x;

    __shared__ float s[8][32];
    __shared__ float sc[8];
    __shared__ float red[32];
    __shared__ float scnt;
    __shared__ float smean[2][Cn];
    __shared__ float srn[2];

    {   // 256 threads = 32 slots x 8 groups of 16 tiles
        const int slot = tid & 31, g = tid >> 5;
        const float* base = &g_part[z][b][slot][0] + g * 16;
        float a = 0.f;
#pragma unroll
        for (int k = 0; k < 4; k++) {
            const float4 v = *(const float4*)(base + 4 * k);
            a += (v.x + v.y) + (v.z + v.w);
        }
        s[g][slot] = a;
    }
    if (tid < 8) {
        const float* cb = &g_cnt[b][0] + tid * 16;
        float a = 0.f;
#pragma unroll
        for (int k = 0; k < 4; k++) {
            const float4 v = *(const float4*)(cb + 4 * k);
            a += (v.x + v.y) + (v.z + v.w);
        }
        sc[tid] = a;
    }
    __syncthreads();
    if (tid < 32) {
        float a = 0.f;
#pragma unroll
        for (int g = 0; g < 8; g++) a += s[g][tid];
        red[tid] = a;
    } else if (tid == 32) {
        float a = 0.f;
#pragma unroll
        for (int g = 0; g < 8; g++) a += sc[g];
        scnt = a;
    }
    __syncthreads();
    if (tid < 2) {
        const int cls = tid;
        const float cnt0 = scnt;
        const float cnt  = cls ? ((float)HWn - cnt0) : cnt0;
        const float inv  = 1.0f / (cnt + 1e-6f);
        float nm2 = 0.f;
#pragma unroll
        for (int c = 0; c < Cn; c++) {
            const float tot = red[c], s0 = red[16 + c];
            const float sv  = cls ? (tot - s0) : s0;
            const float m   = sv * inv;
            smean[cls][c] = m;
            nm2 = fmaf(m, m, nm2);
        }
        srn[cls] = 1.0f / fmaxf(sqrtf(nm2), 1e-8f);
    }
    __syncthreads();
    if (tid < Cn) {
        g_dm[z][b][tid] = smean[0][tid] * srn[0] - smean[1][tid] * srn[1];
    }
}

// ---------------------------------------------------------------------------
// Pass 3 (PDL secondary): waits on finalize only before reading g_dm/g_is32;
// interleaved S/T channel loop; MSE with last-block writeout.
// grid (T3, Bn); 4 px/thread, float4 loads.
// ---------------------------------------------------------------------------
__global__ void __launch_bounds__(THR, 8)
pass3_kernel(const float* __restrict__ S, const float* __restrict__ T,
             const int* __restrict__ TW, float* __restrict__ out) {
    // PDL: block until the upstream (finalize) grid's writes are visible.
    cudaGridDependencySynchronize();

    const int tile = blockIdx.x, b = blockIdx.y;
    const int tid  = threadIdx.x;

    __shared__ float sdM[2][Cn];
    __shared__ int sis32;
    __shared__ unsigned int slast;
    if (tid < 32) {
        const int z = tid >> 4, c = tid & 15;
        sdM[z][c] = g_dm[z][b][c];
    } else if (tid == 32) {
        sis32 = g_is32;
    }
    __syncthreads();
    const int is32 = sis32;

    const float* Sb  = S + ((size_t)b << 20);
    const float* Tb  = T + ((size_t)b << 20);
    const int*   twb = TW + (is32 ? ((size_t)b << 16) : ((size_t)b << 17));

    const int p = tile * PPB + tid * 4;
    int c0, c1, c2, c3;
    load_cls4(twb, p, is32, c0, c1, c2, c3);
    const float s0 = (c0 == 0) ? 1.f : -1.f;
    const float s1 = (c1 == 0) ? 1.f : -1.f;
    const float s2 = (c2 == 0) ? 1.f : -1.f;
    const float s3 = (c3 == 0) ? 1.f : -1.f;

    // Interleaved S/T channel loop: independent accumulator sets.
    float nS0 = 0.f, nS1 = 0.f, nS2 = 0.f, nS3 = 0.f;
    float dS0 = 0.f, dS1 = 0.f, dS2 = 0.f, dS3 = 0.f;
    float nT0 = 0.f, nT1 = 0.f, nT2 = 0.f, nT3 = 0.f;
    float dT0 = 0.f, dT1 = 0.f, dT2 = 0.f, dT3 = 0.f;
#pragma unroll
    for (int c = 0; c < Cn; c++) {
        const float4 vs = ldcs4(Sb + ((size_t)c << 16) + p);
        const float4 vt = ldcs4(Tb + ((size_t)c << 16) + p);
        const float mS = sdM[0][c], mT = sdM[1][c];
        nS0 = fmaf(vs.x, vs.x, nS0); nS1 = fmaf(vs.y, vs.y, nS1);
        nS2 = fmaf(vs.z, vs.z, nS2); nS3 = fmaf(vs.w, vs.w, nS3);
        dS0 = fmaf(vs.x, mS, dS0);   dS1 = fmaf(vs.y, mS, dS1);
        dS2 = fmaf(vs.z, mS, dS2);   dS3 = fmaf(vs.w, mS, dS3);
        nT0 = fmaf(vt.x, vt.x, nT0); nT1 = fmaf(vt.y, vt.y, nT1);
        nT2 = fmaf(vt.z, vt.z, nT2); nT3 = fmaf(vt.w, vt.w, nT3);
        dT0 = fmaf(vt.x, mT, dT0);   dT1 = fmaf(vt.y, mT, dT1);
        dT2 = fmaf(vt.z, mT, dT2);   dT3 = fmaf(vt.w, mT, dT3);
    }

    const float e0 = __expf(s0 * dS0 * rsqrtf(fmaxf(nS0, 1e-24f)))
                   - __expf(s0 * dT0 * rsqrtf(fmaxf(nT0, 1e-24f)));
    const float e1 = __expf(s1 * dS1 * rsqrtf(fmaxf(nS1, 1e-24f)))
                   - __expf(s1 * dT1 * rsqrtf(fmaxf(nT1, 1e-24f)));
    const float e2 = __expf(s2 * dS2 * rsqrtf(fmaxf(nS2, 1e-24f)))
                   - __expf(s2 * dT2 * rsqrtf(fmaxf(nT2, 1e-24f)));
    const float e3 = __expf(s3 * dS3 * rsqrtf(fmaxf(nS3, 1e-24f)))
                   - __expf(s3 * dT3 * rsqrtf(fmaxf(nT3, 1e-24f)));
    float acc = fmaf(e0, e0, e1 * e1) + fmaf(e2, e2, e3 * e3);

    // Block reduce MSE partial, then last-block final reduction.
    __shared__ float smse[THR / 32];
    acc = wred(acc);
    const int lane = tid & 31, w = tid >> 5;
    if (lane == 0) smse[w] = acc;
    __syncthreads();
    const int gid = b * T3 + tile;
    if (tid == 0) {
        float sv = 0.f;
#pragma unroll
        for (int ww = 0; ww < THR / 32; ww++) sv += smse[ww];
        g_msep[gid] = sv;
        __threadfence();
        const unsigned int old = atomicAdd(&g_done, 1u);
        slast = (old == (unsigned int)(Bn * T3 - 1)) ? 1u : 0u;
    }
    __syncthreads();

    if (slast) {
        volatile float* mp = &g_msep[0];
        double d = 0.0;
#pragma unroll
        for (int k = 0; k < (Bn * T3) / THR; k++)
            d += (double)mp[tid * ((Bn * T3) / THR) + k];
        d = wredd(d);
        __shared__ double sd[THR / 32];
        if (lane == 0) sd[w] = d;
        __syncthreads();
        if (tid == 0) {
            double tot = 0.0;
#pragma unroll
            for (int ww = 0; ww < THR / 32; ww++) tot += sd[ww];
            out[0] = (float)(tot * (1.0 / ((double)Bn * (double)HWn)));
            g_done = 0;   // reset for next graph replay
        }
    }
}

extern "C" void kernel_launch(void* const* d_in, const int* in_sizes, int n_in,
                              void* d_out, int out_size) {
    const float* S  = (const float*)d_in[0];
    const float* T  = (const float*)d_in[1];
    const int*   TW = (const int*)d_in[2];
    float* out = (float*)d_out;

    // pass1: normal launch.
    dim3 g1(T1, Bn, 2);
    pass1_kernel<<<g1, THR>>>(S, T, TW);

    // finalize + pass3: programmatic dependent launches (overlap launch
    // latency and the tiny finalize with the big kernels' tails).
    cudaLaunchAttribute attr[1];
    attr[0].id = cudaLaunchAttributeProgrammaticStreamSerialization;
    attr[0].val.programmaticStreamSerializationAllowed = 1;

    {
        cudaLaunchConfig_t cfg = {};
        cfg.gridDim = dim3(Bn, 2);
        cfg.blockDim = dim3(256);
        cfg.attrs = attr;
        cfg.numAttrs = 1;
        cudaLaunchKernelEx(&cfg, finalize_kernel);
    }
    {
        cudaLaunchConfig_t cfg = {};
        cfg.gridDim = dim3(T3, Bn);
        cfg.blockDim = dim3(THR);
        cfg.attrs = attr;
        cfg.numAttrs = 1;
        cudaLaunchKernelEx(&cfg, pass3_kernel, S, T, TW, out);
    }
}